// round 10
// baseline (speedup 1.0000x reference)
#include <cuda_runtime.h>
#include <cuda_bf16.h>

#define N_NODES 10000
#define N_EDGES 640000
#define D 128
#define D4 (D/4)
#define CAP 256          // bucket capacity per node (max in-degree ~110)
#define TILE_M 32        // nodes per fused block

typedef unsigned long long u64;

// ---------------- scratch (static device globals; no allocation) -------------
__device__ int   g_deg_out[N_NODES];
__device__ int   g_cnt_in [N_NODES];
__device__ int2  g_bucket[N_NODES * CAP];     // {src, ew_bits} per in-edge
__device__ __nv_bfloat16 g_xb [N_NODES * D];  // bf16 features pre-scaled by norm_src
__device__ __nv_bfloat16 g_h1b[N_NODES * D];  // bf16 layer-1 out pre-scaled by norm_src

// ---------------- f32x2 helpers ----------------------------------------------
__device__ __forceinline__ u64 packf2(float lo, float hi) {
    u64 r; asm("mov.b64 %0, {%1, %2};" : "=l"(r) : "f"(lo), "f"(hi)); return r;
}
__device__ __forceinline__ void ffma2(u64& d, u64 a, u64 b) {
    asm("fma.rn.f32x2 %0, %1, %2, %3;" : "=l"(d) : "l"(a), "l"(b), "l"(d));
}
__device__ __forceinline__ float unpack_sum(u64 v) {
    float lo, hi; asm("mov.b64 {%0, %1}, %2;" : "=f"(lo), "=f"(hi) : "l"(v));
    return lo + hi;
}

// ---------------- kernels ----------------------------------------------------

__global__ void k_zero() {
    int i = blockIdx.x * blockDim.x + threadIdx.x;
    if (i < N_NODES) { g_deg_out[i] = 0; g_cnt_in[i] = 0; }
}

// single edge pass: out-degree count + in-bucket placement (count == slot).
__global__ void k_fill(const int* __restrict__ src, const int* __restrict__ dst,
                       const float* __restrict__ ew) {
    int t = blockIdx.x * blockDim.x + threadIdx.x;
    if (t < N_EDGES / 2) {
        int2   s = ((const int2*)src)[t];
        int2   d = ((const int2*)dst)[t];
        float2 w = ((const float2*)ew)[t];
        atomicAdd(&g_deg_out[s.x], 1);
        atomicAdd(&g_deg_out[s.y], 1);
        int p0 = atomicAdd(&g_cnt_in[d.x], 1);
        int p1 = atomicAdd(&g_cnt_in[d.y], 1);
        if (p0 < CAP) g_bucket[(d.x << 8) + p0] = make_int2(s.x, __float_as_int(w.x));
        if (p1 < CAP) g_bucket[(d.y << 8) + p1] = make_int2(s.y, __float_as_int(w.y));
    }
}

// g_xb = bf16( x * rsqrt(max(deg_out,1)) )  — norm computed on the fly
__global__ void k_scale(const float* __restrict__ x) {
    int idx = blockIdx.x * blockDim.x + threadIdx.x;   // over float4 chunks
    if (idx < N_NODES * D4) {
        int row = idx >> 5;
        float ns = rsqrtf(fmaxf((float)g_deg_out[row], 1.0f));
        float4 v = ((const float4*)x)[idx];
        __nv_bfloat162 lo = __floats2bfloat162_rn(v.x * ns, v.y * ns);
        __nv_bfloat162 hi = __floats2bfloat162_rn(v.z * ns, v.w * ns);
        uint2 packed;
        packed.x = *reinterpret_cast<unsigned*>(&lo);
        packed.y = *reinterpret_cast<unsigned*>(&hi);
        ((uint2*)g_xb)[idx] = packed;
    }
}

__device__ __forceinline__ void fma_bf16x4(float4& acc, uint2 v, float w) {
    float2 lo = __bfloat1622float2(*reinterpret_cast<__nv_bfloat162*>(&v.x));
    float2 hi = __bfloat1622float2(*reinterpret_cast<__nv_bfloat162*>(&v.y));
    acc.x = fmaf(lo.x, w, acc.x);
    acc.y = fmaf(lo.y, w, acc.y);
    acc.z = fmaf(hi.x, w, acc.z);
    acc.w = fmaf(hi.y, w, acc.w);
}

// Fused aggregate + GEMM + epilogue for one layer.
// 256 threads = 8 warps. Each warp aggregates 4 nodes straight into the smem
// tile; then the block does (tile @ W) * norm_dst + b, relu (f32x2 inner loop).
// LAYER0: gather g_xb, write g_h1b (pre-scaled by norm_src for next layer);
// else:   gather g_h1b, write fp32 out.
template <bool LAYER0>
__global__ void __launch_bounds__(256)
k_layer(const float* __restrict__ W, const float* __restrict__ b,
        float* __restrict__ outf) {
    __shared__ float sm[TILE_M][D];
    int t    = threadIdx.x;
    int warp = t >> 5, lane = t & 31;
    int m0   = blockIdx.x * TILE_M;
    const uint2* h2 = LAYER0 ? (const uint2*)g_xb : (const uint2*)g_h1b;

    // ---- phase 1: aggregation (warp per node, 4 nodes per warp) ----------
    #pragma unroll
    for (int r = warp * 4; r < warp * 4 + 4; ++r) {
        int node = m0 + r;
        float4 acc = make_float4(0.f, 0.f, 0.f, 0.f);
        if (node < N_NODES) {
            int cnt = g_cnt_in[node];
            int end = cnt < CAP ? cnt : CAP;
            const int2* bk = g_bucket + (node << 8);
            int e = 0;
            for (; e + 7 < end; e += 8) {
                int2  bi[8];
                uint2 vi[8];
                #pragma unroll
                for (int j = 0; j < 8; ++j) bi[j] = bk[e + j];
                #pragma unroll
                for (int j = 0; j < 8; ++j) vi[j] = h2[bi[j].x * D4 + lane];
                #pragma unroll
                for (int j = 0; j < 8; ++j) fma_bf16x4(acc, vi[j], __int_as_float(bi[j].y));
            }
            for (; e < end; ++e) {
                int2  bb = bk[e];
                uint2 v  = h2[bb.x * D4 + lane];
                fma_bf16x4(acc, v, __int_as_float(bb.y));
            }
        }
        *(float4*)&sm[r][lane * 4] = acc;
    }
    __syncthreads();

    // ---- phase 2: GEMM 32x128 @ 128x128 ----------------------------------
    int n  = t & 127;        // output column
    int mh = t >> 7;         // row half: 0 -> rows 0..15, 1 -> rows 16..31
    u64 acc2[16];
    #pragma unroll
    for (int m = 0; m < 16; ++m) acc2[m] = 0ull;

    for (int kb = 0; kb < D; kb += 4) {
        float w0 = W[(kb + 0) * D + n];
        float w1 = W[(kb + 1) * D + n];
        float w2 = W[(kb + 2) * D + n];
        float w3 = W[(kb + 3) * D + n];
        u64 b01 = packf2(w0, w1);
        u64 b23 = packf2(w2, w3);
        #pragma unroll
        for (int m = 0; m < 16; ++m) {
            union { float4 f; u64 u[2]; } a;
            a.f = *(const float4*)&sm[mh * 16 + m][kb];
            ffma2(acc2[m], a.u[0], b01);
            ffma2(acc2[m], a.u[1], b23);
        }
    }

    // ---- epilogue ---------------------------------------------------------
    float bias = b[n];
    #pragma unroll
    for (int m = 0; m < 16; ++m) {
        int row = m0 + mh * 16 + m;
        if (row < N_NODES) {
            float nd = rsqrtf(fmaxf((float)g_cnt_in[row], 1.0f));
            float r  = fmaxf(unpack_sum(acc2[m]) * nd + bias, 0.0f);
            if (LAYER0) {
                float ns = rsqrtf(fmaxf((float)g_deg_out[row], 1.0f));
                g_h1b[row * D + n] = __float2bfloat16(r * ns);
            } else {
                outf[row * D + n] = r;
            }
        }
    }
}

// ---------------- launch ------------------------------------------------------

extern "C" void kernel_launch(void* const* d_in, const int* in_sizes, int n_in,
                              void* d_out, int out_size) {
    const float* x  = (const float*)d_in[0];
    const float* ew = (const float*)d_in[1];
    const float* W0 = (const float*)d_in[2];
    const float* b0 = (const float*)d_in[3];
    const float* W1 = (const float*)d_in[4];
    const float* b1 = (const float*)d_in[5];
    const int*   src = (const int*)d_in[6];
    const int*   dst = (const int*)d_in[7];
    float* out = (float*)d_out;

    const int NB  = (N_NODES + 255) / 256;           // 40
    const int EB2 = (N_EDGES / 2 + 255) / 256;       // 1250
    const int SB  = (N_NODES * D4 + 255) / 256;      // 1250
    const int LB  = (N_NODES + TILE_M - 1) / TILE_M; // 313

    k_zero  <<<NB, 256>>>();
    k_fill  <<<EB2, 256>>>(src, dst, ew);
    k_scale <<<SB, 256>>>(x);

    k_layer<true> <<<LB, 256>>>(W0, b0, nullptr);  // xb  -> h1b
    k_layer<false><<<LB, 256>>>(W1, b1, out);      // h1b -> out

    (void)in_sizes; (void)n_in; (void)out_size;
}

// round 11
// speedup vs baseline: 1.1508x; 1.1508x over previous
#include <cuda_runtime.h>
#include <cuda_bf16.h>

#define N_NODES 10000
#define N_EDGES 640000
#define D 128
#define D4 (D/4)
#define CAP 256          // bucket capacity per node (max in-degree ~110)
#define TILE_M 16        // nodes per fused block -> 625 blocks

typedef unsigned long long u64;

// ---------------- scratch (static device globals; no allocation) -------------
__device__ int   g_deg_out[N_NODES];
__device__ int   g_cnt_in [N_NODES];
__device__ int2  g_bucket[N_NODES * CAP];     // {src, ew_bits} per in-edge
__device__ __nv_bfloat16 g_xb [N_NODES * D];  // bf16 features pre-scaled by norm_src
__device__ __nv_bfloat16 g_h1b[N_NODES * D];  // bf16 layer-1 out pre-scaled by norm_src

// ---------------- f32x2 helpers ----------------------------------------------
__device__ __forceinline__ u64 packf2(float lo, float hi) {
    u64 r; asm("mov.b64 %0, {%1, %2};" : "=l"(r) : "f"(lo), "f"(hi)); return r;
}
__device__ __forceinline__ void ffma2(u64& d, u64 a, u64 b) {
    asm("fma.rn.f32x2 %0, %1, %2, %3;" : "=l"(d) : "l"(a), "l"(b), "l"(d));
}
__device__ __forceinline__ float unpack_sum(u64 v) {
    float lo, hi; asm("mov.b64 {%0, %1}, %2;" : "=f"(lo), "=f"(hi) : "l"(v));
    return lo + hi;
}

// ---------------- kernels ----------------------------------------------------

__global__ void k_zero() {
    int i = blockIdx.x * blockDim.x + threadIdx.x;
    if (i < N_NODES) { g_deg_out[i] = 0; g_cnt_in[i] = 0; }
}

// single edge pass: out-degree count + in-bucket placement (count == slot).
__global__ void k_fill(const int* __restrict__ src, const int* __restrict__ dst,
                       const float* __restrict__ ew) {
    int t = blockIdx.x * blockDim.x + threadIdx.x;
    if (t < N_EDGES / 2) {
        int2   s = ((const int2*)src)[t];
        int2   d = ((const int2*)dst)[t];
        float2 w = ((const float2*)ew)[t];
        atomicAdd(&g_deg_out[s.x], 1);
        atomicAdd(&g_deg_out[s.y], 1);
        int p0 = atomicAdd(&g_cnt_in[d.x], 1);
        int p1 = atomicAdd(&g_cnt_in[d.y], 1);
        if (p0 < CAP) g_bucket[(d.x << 8) + p0] = make_int2(s.x, __float_as_int(w.x));
        if (p1 < CAP) g_bucket[(d.y << 8) + p1] = make_int2(s.y, __float_as_int(w.y));
    }
}

// g_xb = bf16( x * rsqrt(max(deg_out,1)) )
__global__ void k_scale(const float* __restrict__ x) {
    int idx = blockIdx.x * blockDim.x + threadIdx.x;   // over float4 chunks
    if (idx < N_NODES * D4) {
        int row = idx >> 5;
        float ns = rsqrtf(fmaxf((float)g_deg_out[row], 1.0f));
        float4 v = ((const float4*)x)[idx];
        __nv_bfloat162 lo = __floats2bfloat162_rn(v.x * ns, v.y * ns);
        __nv_bfloat162 hi = __floats2bfloat162_rn(v.z * ns, v.w * ns);
        uint2 packed;
        packed.x = *reinterpret_cast<unsigned*>(&lo);
        packed.y = *reinterpret_cast<unsigned*>(&hi);
        ((uint2*)g_xb)[idx] = packed;
    }
}

__device__ __forceinline__ void fma_bf16x4(float4& acc, uint2 v, float w) {
    float2 lo = __bfloat1622float2(*reinterpret_cast<__nv_bfloat162*>(&v.x));
    float2 hi = __bfloat1622float2(*reinterpret_cast<__nv_bfloat162*>(&v.y));
    acc.x = fmaf(lo.x, w, acc.x);
    acc.y = fmaf(lo.y, w, acc.y);
    acc.z = fmaf(hi.x, w, acc.z);
    acc.w = fmaf(hi.y, w, acc.w);
}

// Fused aggregate + GEMM + epilogue for one layer.
// 256 threads = 8 warps, TILE_M=16 nodes per block (2 per warp).
// Agg: bucket entries loaded coalesced (1 per lane per 32-edge chunk) and
// distributed via shuffle; zero-padded lanes give w=0 (harmless fma).
// GEMM: 16x128 @ 128x128, f32x2 packed inner loop, 8 rows per thread.
template <bool LAYER0>
__global__ void __launch_bounds__(256)
k_layer(const float* __restrict__ W, const float* __restrict__ b,
        float* __restrict__ outf) {
    __shared__ float sm[TILE_M][D];
    int t    = threadIdx.x;
    int warp = t >> 5, lane = t & 31;
    int m0   = blockIdx.x * TILE_M;
    const uint2* h2 = LAYER0 ? (const uint2*)g_xb : (const uint2*)g_h1b;

    // ---- phase 1: aggregation (2 nodes per warp) --------------------------
    #pragma unroll
    for (int r = warp * 2; r < warp * 2 + 2; ++r) {
        int node = m0 + r;
        float4 acc = make_float4(0.f, 0.f, 0.f, 0.f);
        if (node < N_NODES) {
            int cnt = g_cnt_in[node];
            int end = cnt < CAP ? cnt : CAP;
            const int2* bk = g_bucket + (node << 8);
            for (int base = 0; base < end; base += 32) {
                int2 bb = (base + lane < end) ? bk[base + lane]
                                              : make_int2(0, 0); // w=0 pad
                int lim = end - base;  if (lim > 32) lim = 32;
                int nch = (lim + 7) >> 3;
                for (int c = 0; c < nch; ++c) {
                    int   si[8];
                    float wi[8];
                    uint2 vi[8];
                    #pragma unroll
                    for (int j = 0; j < 8; ++j) {
                        int jj = c * 8 + j;
                        si[j] = __shfl_sync(0xffffffffu, bb.x, jj);
                        wi[j] = __int_as_float(__shfl_sync(0xffffffffu, bb.y, jj));
                    }
                    #pragma unroll
                    for (int j = 0; j < 8; ++j) vi[j] = h2[si[j] * D4 + lane];
                    #pragma unroll
                    for (int j = 0; j < 8; ++j) fma_bf16x4(acc, vi[j], wi[j]);
                }
            }
        }
        *(float4*)&sm[r][lane * 4] = acc;
    }
    __syncthreads();

    // ---- phase 2: GEMM 16x128 @ 128x128 ----------------------------------
    int n  = t & 127;        // output column
    int mh = t >> 7;         // 0 -> rows 0..7, 1 -> rows 8..15
    u64 acc2[8];
    #pragma unroll
    for (int m = 0; m < 8; ++m) acc2[m] = 0ull;

    for (int kb = 0; kb < D; kb += 4) {
        float w0 = W[(kb + 0) * D + n];
        float w1 = W[(kb + 1) * D + n];
        float w2 = W[(kb + 2) * D + n];
        float w3 = W[(kb + 3) * D + n];
        u64 b01 = packf2(w0, w1);
        u64 b23 = packf2(w2, w3);
        #pragma unroll
        for (int m = 0; m < 8; ++m) {
            union { float4 f; u64 u[2]; } a;
            a.f = *(const float4*)&sm[mh * 8 + m][kb];
            ffma2(acc2[m], a.u[0], b01);
            ffma2(acc2[m], a.u[1], b23);
        }
    }

    // ---- epilogue ---------------------------------------------------------
    float bias = b[n];
    #pragma unroll
    for (int m = 0; m < 8; ++m) {
        int row = m0 + mh * 8 + m;
        if (row < N_NODES) {
            float nd = rsqrtf(fmaxf((float)g_cnt_in[row], 1.0f));
            float r  = fmaxf(unpack_sum(acc2[m]) * nd + bias, 0.0f);
            if (LAYER0) {
                float ns = rsqrtf(fmaxf((float)g_deg_out[row], 1.0f));
                g_h1b[row * D + n] = __float2bfloat16(r * ns);
            } else {
                outf[row * D + n] = r;
            }
        }
    }
}

// ---------------- launch ------------------------------------------------------

extern "C" void kernel_launch(void* const* d_in, const int* in_sizes, int n_in,
                              void* d_out, int out_size) {
    const float* x  = (const float*)d_in[0];
    const float* ew = (const float*)d_in[1];
    const float* W0 = (const float*)d_in[2];
    const float* b0 = (const float*)d_in[3];
    const float* W1 = (const float*)d_in[4];
    const float* b1 = (const float*)d_in[5];
    const int*   src = (const int*)d_in[6];
    const int*   dst = (const int*)d_in[7];
    float* out = (float*)d_out;

    const int NB  = (N_NODES + 255) / 256;           // 40
    const int EB2 = (N_EDGES / 2 + 255) / 256;       // 1250
    const int SB  = (N_NODES * D4 + 255) / 256;      // 1250
    const int LB  = (N_NODES + TILE_M - 1) / TILE_M; // 625

    k_zero  <<<NB, 256>>>();
    k_fill  <<<EB2, 256>>>(src, dst, ew);
    k_scale <<<SB, 256>>>(x);

    k_layer<true> <<<LB, 256>>>(W0, b0, nullptr);  // xb  -> h1b
    k_layer<false><<<LB, 256>>>(W1, b1, out);      // h1b -> out

    (void)in_sizes; (void)n_in; (void)out_size;
}